// round 16
// baseline (speedup 1.0000x reference)
#include <cuda_runtime.h>
#include <cstdint>

// ---------------- problem constants ----------------
#define TOTAL   340704u        // 16224 + 64896 + 259584 candidates
#define OFF1    16224u
#define OFF2    81120u
#define KSEL    512u
#define NBOX    1536
#define NWORD   24             // 1536/64 mask words per row
#define BINBASE 0xBF199u       // (bits(0.6)|sign)>>12 ; keys for obj in (0.6,1]
#define NBIN    1640u          // 0xBF800 - 0xBF199 + 1
#define NBINP   1664u          // padded
#define POOLCAP 65536u
#define SORTCAP 4096

typedef unsigned long long u64;
typedef uint32_t u32;

// ---------------- device scratch (static, allocation-free) ----------------
// Zero-initialized at module load; k_nms_out re-zeroes at the end of every
// run, so every execution starts from zeroed state (deterministic).
__device__ u32   g_hist[3*NBINP];
__device__ u32   g_validCount[3];
__device__ int   g_binB[3];
__device__ u32   g_selCount[3];
__device__ u32   g_poolCount[3];
__device__ u32   g_ticket;
__device__ u64   g_sel[3*512];
__device__ u64   g_pool[3*POOLCAP];
__device__ u64   g_sorted[NBOX];
__device__ float g_boxes[NBOX*9];
__device__ float g_nmsb[NBOX*5];     // x1,y1,x2,y2,area
__device__ int   g_valid[NBOX];
__device__ u64   g_maskT[NBOX*NWORD]; // TRANSPOSED: [col i][row-word w]

// ---------------- shared address/key computation ----------------
__device__ __forceinline__ void cand_addr(u32 i,
        const float* __restrict__ o13, const float* __restrict__ o26,
        const float* __restrict__ o52,
        float& x, int& s, u32& orig) {
    if (i < OFF1) {                 // H=13, HW=169, NHW=5408
        u32 loc = i;
        u32 a = loc / 5408u, r = loc - a*5408u;
        u32 n = r / 169u,  hw = r - n*169u;
        x = o13[(n*255u + a*85u)*169u + hw]; s = 0; orig = r*3u + a;
    } else if (i < OFF2) {          // H=26, HW=676, NHW=21632
        u32 loc = i - OFF1;
        u32 a = loc / 21632u, r = loc - a*21632u;
        u32 n = r / 676u,  hw = r - n*676u;
        x = o26[(n*255u + a*85u)*676u + hw]; s = 1; orig = r*3u + a;
    } else {                        // H=52, HW=2704, NHW=86528
        u32 loc = i - OFF2;
        u32 a = loc / 86528u, r = loc - a*86528u;
        u32 n = r / 2704u, hw = r - n*2704u;
        x = o52[(n*255u + a*85u)*2704u + hw]; s = 2; orig = r*3u + a;
    }
}

// ---------------- K1: histogram + (last-block tail) threshold-bin scan ----------------
__global__ __launch_bounds__(256) void k_hist(const float* __restrict__ o13,
                                              const float* __restrict__ o26,
                                              const float* __restrict__ o52) {
    __shared__ u32 sh[3*NBINP];
    __shared__ u32 svc[3];
    __shared__ u32 isLast;
    const u32 t = threadIdx.x;
    for (u32 b = t; b < 3u*NBINP; b += 256u) sh[b] = 0u;
    if (t < 3u) svc[t] = 0u;
    __syncthreads();
    for (u32 i = blockIdx.x*256u + t; i < TOTAL; i += 65536u) {
        float x; int s; u32 orig;
        cand_addr(i, o13, o26, o52, x, s, orig);
        float obj = 1.f / (1.f + expf(-x));
        if (obj > 0.6f) {
            u32 key = __float_as_uint(obj) | 0x80000000u;
            atomicAdd(&sh[(u32)s*NBINP + ((key >> 12) - BINBASE)], 1u);
            atomicAdd(&svc[s], 1u);
        }
    }
    __syncthreads();
    for (u32 b = t; b < 3u*NBINP; b += 256u) {
        u32 v = sh[b];
        if (v) atomicAdd(&g_hist[b], v);
    }
    if (t < 3u && svc[t]) atomicAdd(&g_validCount[t], svc[t]);
    __threadfence();
    __syncthreads();
    if (t == 0) isLast = (atomicAdd(&g_ticket, 1u) == gridDim.x - 1u);
    __syncthreads();
    if (!isLast) return;

    // ---- tail: per-scale threshold bin via suffix scan (256 threads) ----
    u32* ss = sh;                                  // reuse smem
    for (int s = 0; s < 3; s++) {
        __syncthreads();
        if (g_validCount[s] < KSEL) { if (t == 0) g_binB[s] = -2; continue; }
        const u32* hist = g_hist + (u32)s*NBINP;
        u32 b0 = t * 7u;
        u32 part = 0u;
        #pragma unroll
        for (u32 k = 0; k < 7u; k++) {
            u32 b = b0 + k;
            if (b < NBIN) part += hist[b];
        }
        ss[t] = part;
        __syncthreads();
        for (u32 off = 1; off < 256u; off <<= 1) {  // inclusive suffix scan
            u32 add = (t + off < 256u) ? ss[t + off] : 0u;
            __syncthreads();
            ss[t] += add;
            __syncthreads();
        }
        u32 S = ss[t];
        u32 Sn = (t < 255u) ? ss[t + 1] : 0u;
        if (S >= KSEL && Sn < KSEL) {
            u32 cum = Sn;
            for (int k = 6; k >= 0; k--) {
                u32 b = b0 + (u32)k;
                if (b < NBIN) {
                    u32 c = hist[b];
                    cum += c;
                    if (cum >= KSEL) { g_binB[s] = (int)b; break; }
                }
            }
        }
    }
    if (t == 0) g_ticket = 0u;                     // reset for next run
}

// ---------------- K2: select / pool (threshold bins precomputed) ----------------
__global__ __launch_bounds__(256) void k_select(const float* __restrict__ o13,
                                                const float* __restrict__ o26,
                                                const float* __restrict__ o52) {
    const int b0 = g_binB[0], b1 = g_binB[1], b2 = g_binB[2];
    for (u32 i = blockIdx.x*256u + threadIdx.x; i < TOTAL; i += 65536u) {
        float x; int s; u32 orig;
        cand_addr(i, o13, o26, o52, x, s, orig);
        float obj = 1.f / (1.f + expf(-x));
        if (!(obj > 0.6f)) continue;
        u32 key = __float_as_uint(obj) | 0x80000000u;
        int hidx = (int)((key >> 12) - BINBASE);
        int tb = (s == 0) ? b0 : (s == 1) ? b1 : b2;
        if (hidx > tb) {
            u32 pos = atomicAdd(&g_selCount[s], 1u);
            g_sel[(u32)s*512u + pos] = ((u64)key << 32) | orig;
        } else if (hidx == tb) {
            u32 pos = atomicAdd(&g_poolCount[s], 1u);
            if (pos < POOLCAP)
                g_pool[(u32)s*POOLCAP + pos] = ((u64)key << 32) | (u32)(~orig);
        }
    }
}

// ---------------- K3: threshold-bin top-off + rank-scatter global order ----------------
__global__ __launch_bounds__(1024) void k_sortfix() {
    __shared__ __align__(16) u64 sm[SORTCAP];  // 32 KB (pool sort / rank values)
    __shared__ u32 sTot[3];
    __shared__ u32 scnt, srank;
    const u32 t = threadIdx.x;
    for (int s = 0; s < 3; s++) {
        u32 direct = g_selCount[s];
        u32 valid  = g_validCount[s];
        u32 need   = (valid >= KSEL) ? (KSEL - direct) : 0u;
        if (t == 0) sTot[s] = direct + need;
        u32 n = g_poolCount[s]; if (n > POOLCAP) n = POOLCAP;
        if (need > 0u) {
            if (n <= (u32)SORTCAP) {
                u32 P = 2u; while (P < n) P <<= 1u;
                for (u32 i = t; i < P; i += 1024u)
                    sm[i] = (i < n) ? g_pool[(u32)s*POOLCAP + i] : 0ull;
                __syncthreads();
                for (u32 k = 2; k <= P; k <<= 1)
                    for (u32 j = k >> 1; j > 0; j >>= 1) {
                        for (u32 i = t; i < P; i += 1024u) {
                            u32 ixj = i ^ j;
                            if (ixj > i) {
                                bool desc = ((i & k) == 0u);
                                u64 x = sm[i], y = sm[ixj];
                                if (desc ? (x < y) : (x > y)) { sm[i] = y; sm[ixj] = x; }
                            }
                        }
                        __syncthreads();
                    }
                for (u32 j = t; j < need; j += 1024u) {
                    u64 v = sm[j];
                    g_sel[(u32)s*512u + direct + j] =
                        (v & 0xFFFFFFFF00000000ull) | (u32)(~(u32)v);
                }
            } else {
                // fallback: exact selection via 64-bit binary search (v unique)
                u64 lo = 1ull, hi = 0xFFFFFFFFFFFFFFFFull;
                while (lo < hi) {
                    u64 mid = lo + ((hi - lo + 1ull) >> 1);
                    if (t == 0) scnt = 0u;
                    __syncthreads();
                    u32 c = 0u;
                    for (u32 j = t; j < n; j += 1024u)
                        if (g_pool[(u32)s*POOLCAP + j] >= mid) c++;
                    if (c) atomicAdd(&scnt, c);
                    __syncthreads();
                    u32 total = scnt;
                    __syncthreads();
                    if (total >= need) lo = mid; else hi = mid - 1ull;
                }
                if (t == 0) srank = 0u;
                __syncthreads();
                for (u32 j = t; j < n; j += 1024u) {
                    u64 v = g_pool[(u32)s*POOLCAP + j];
                    if (v >= lo) {
                        u32 p = atomicAdd(&srank, 1u);
                        if (p < need)
                            g_sel[(u32)s*512u + direct + p] =
                                (v & 0xFFFFFFFF00000000ull) | (u32)(~(u32)v);
                    }
                }
            }
        }
        __syncthreads();
    }
    // ---- global order via rank-scatter (values globally unique) ----
    // filled slot: v = key<<32 | ~gidx (MSB set). empty slot: v = slot index
    // (< 2^32 -> ranks after all real entries; key field reads as 0).
    const u32 offc[3] = {0u, OFF1, OFF2};
    for (u32 j = t; j < (u32)NBOX; j += 1024u) {
        u32 s = j >> 9, p = j & 511u;
        u64 v;
        if (p < sTot[s]) {
            u64 e = g_sel[s*512u + p];
            u32 key  = (u32)(e >> 32);
            u32 gidx = offc[s] + (u32)e;
            v = ((u64)key << 32) | (u32)(~gidx);
        } else {
            v = (u64)j;
        }
        sm[j] = v;
    }
    __syncthreads();
    // thread t ranks slots t and t+1024 (lockstep smem broadcast scan)
    {
        u64 m0 = sm[t];
        u64 m1 = (t + 1024u < (u32)NBOX) ? sm[t + 1024u] : 0ull;
        u32 r0 = 0u, r1 = 0u;
        for (int j = 0; j < NBOX; j++) {
            u64 v = sm[j];
            r0 += (v > m0) ? 1u : 0u;
            r1 += (v > m1) ? 1u : 0u;
        }
        g_sorted[r0] = m0;
        if (t + 1024u < (u32)NBOX) g_sorted[r1] = m1;
    }
}

// ---------------- K4: decode winners (one warp per box) ----------------
__global__ void k_decode(const float* __restrict__ o13, const float* __restrict__ o26,
                         const float* __restrict__ o52,
                         const float* __restrict__ a13, const float* __restrict__ a26,
                         const float* __restrict__ a52) {
    int r = (blockIdx.x * blockDim.x + threadIdx.x) >> 5;
    int lane = threadIdx.x & 31;
    if (r >= NBOX) return;
    u64 e = g_sorted[r];
    u32 key = (u32)(e >> 32);
    if (key == 0u) {
        if (lane == 0) {
            #pragma unroll
            for (int k = 0; k < 9; k++) g_boxes[r*9+k] = 0.f;
            #pragma unroll
            for (int k = 0; k < 5; k++) g_nmsb[r*5+k] = 0.f;
            g_valid[r] = 0;
        }
        return;
    }
    u32 gidx = ~(u32)e;
    const float* p; const float* anc; int H; float ts; u32 loc;
    if (gidx < OFF1)      { p=o13; anc=a13; H=13; ts=32.f; loc=gidx; }
    else if (gidx < OFF2) { p=o26; anc=a26; H=26; ts=16.f; loc=gidx-OFF1; }
    else                  { p=o52; anc=a52; H=52; ts=8.f;  loc=gidx-OFF2; }
    u32 a = loc % 3u; u32 q = loc / 3u;
    u32 w = q % (u32)H; q /= (u32)H;
    u32 h = q % (u32)H; u32 n = q / (u32)H;
    int HW = H*H;
    const float* base = p + (size_t)(n*255u + a*85u)*HW + h*H + w;
    float aux = 0.f;
    if (lane >= 1 && lane <= 4) aux = base[lane * HW];
    float bv = -1e30f; int bc = 1 << 30;       // argmax 80 classes, first-max
    for (int c = lane; c < 80; c += 32) {
        float v = base[(5 + c) * HW];
        if (v > bv) { bv = v; bc = c; }
    }
    #pragma unroll
    for (int off = 16; off; off >>= 1) {
        float ov = __shfl_down_sync(0xffffffffu, bv, off);
        int   oc = __shfl_down_sync(0xffffffffu, bc, off);
        if (ov > bv || (ov == bv && oc < bc)) { bv = ov; bc = oc; }
    }
    float v1 = __shfl_sync(0xffffffffu, aux, 1);
    float v2 = __shfl_sync(0xffffffffu, aux, 2);
    float v3 = __shfl_sync(0xffffffffu, aux, 3);
    float v4 = __shfl_sync(0xffffffffu, aux, 4);
    if (lane == 0) {
        float obj = __uint_as_float(key ^ 0x80000000u);
        float cx = ((float)w + v1) * ts / 416.0f;
        float cy = ((float)h + v2) * ts / 416.0f;
        float bw = anc[a*2+0] * expf(v3) / 416.0f;
        float bh = anc[a*2+1] * expf(v4) / 416.0f;
        float* B = &g_boxes[r*9];
        B[0]=(float)n; B[1]=cx; B[2]=cy; B[3]=bw; B[4]=bh;
        B[5]=obj; B[6]=(float)bc; B[7]=(float)h; B[8]=(float)w;
        float x1 = cx - bw*0.5f, y1 = cy - bh*0.5f;
        float x2 = cx + bw*0.5f, y2 = cy + bh*0.5f;
        float area = fmaxf(x2-x1, 0.f) * fmaxf(y2-y1, 0.f);
        float* Nn = &g_nmsb[r*5];
        Nn[0]=x1; Nn[1]=y1; Nn[2]=x2; Nn[3]=y2; Nn[4]=area;
        g_valid[r] = 1;
    }
}

// ---------------- K5: TRANSPOSED suppression bitmask ----------------
// g_maskT[c][rb] bit j = (row rb*64+j) < c  AND  iou(row, col c) > 0.7
__global__ void k_maskT() {
    int rb = blockIdx.x, cb = blockIdx.y;   // row block (suppressors), col block
    __shared__ float r0[64], r1[64], r2[64], r3[64], ra[64];
    int t = threadIdx.x;
    int rr = rb*64 + t;
    r0[t]=g_nmsb[rr*5+0]; r1[t]=g_nmsb[rr*5+1]; r2[t]=g_nmsb[rr*5+2];
    r3[t]=g_nmsb[rr*5+3]; ra[t]=g_nmsb[rr*5+4];
    __syncthreads();
    int c = cb*64 + t;
    float x1=g_nmsb[c*5+0], y1=g_nmsb[c*5+1], x2=g_nmsb[c*5+2],
          y2=g_nmsb[c*5+3], ar=g_nmsb[c*5+4];
    u64 bits = 0ull;
    #pragma unroll 4
    for (int j = 0; j < 64; j++) {
        int rj = rb*64 + j;
        if (rj < c) {
            float ix = fmaxf(fminf(x2, r2[j]) - fmaxf(x1, r0[j]), 0.f);
            float iy = fmaxf(fminf(y2, r3[j]) - fmaxf(y1, r1[j]), 0.f);
            float iou = (ix * iy) / fmaxf(fminf(ar, ra[j]), 1e-9f);
            if (iou > 0.7f) bits |= (1ull << j);
        }
    }
    g_maskT[c*NWORD + rb] = bits;
}

// ---------------- K6: NMS via exact Jacobi fixpoint + output + re-zero ----------------
// k <- valid; iterate k <- T(k), T(k)[i] = valid[i] & !OR_{j<i}(k[j] & M[j][i]).
// Unique fixpoint = greedy NMS result; correct prefix grows every iteration.
__global__ __launch_bounds__(1024) void k_nms_out(float* __restrict__ out) {
    __shared__ u32 kw32[48];
    __shared__ u32 valid32[48];
    __shared__ u64 k64[NWORD];
    __shared__ int sChanged;
    const int tid  = threadIdx.x;
    const int lane = tid & 31;

    {
        int i = tid;                               // boxes 0..1023
        u32 b = __ballot_sync(0xffffffffu, g_valid[i] != 0);
        if (lane == 0) { valid32[tid >> 5] = b; kw32[tid >> 5] = b; }
        if (tid < 512) {
            int i2 = 1024 + tid;                   // boxes 1024..1535
            u32 b2 = __ballot_sync(0xffffffffu, g_valid[i2] != 0);
            if (lane == 0) { valid32[32 + (tid >> 5)] = b2; kw32[32 + (tid >> 5)] = b2; }
        }
    }
    __syncthreads();

    for (int it = 0; it < NBOX; it++) {
        if (tid < NWORD) k64[tid] = (u64)kw32[2*tid] | ((u64)kw32[2*tid+1] << 32);
        if (tid == 0) sChanged = 0;
        __syncthreads();
        u32 nb0, nb1 = 0u;
        {
            int i = tid;
            u64 acc = 0ull;
            int wmax = i >> 6;
            const u64* mt = &g_maskT[(size_t)i * NWORD];
            for (int w = 0; w <= wmax; w++) acc |= mt[w] & k64[w];
            bool keep = ((valid32[i >> 5] >> (i & 31)) & 1u) && (acc == 0ull);
            nb0 = __ballot_sync(0xffffffffu, keep);
        }
        if (tid < 512) {
            int i = 1024 + tid;
            u64 acc = 0ull;
            int wmax = i >> 6;
            const u64* mt = &g_maskT[(size_t)i * NWORD];
            for (int w = 0; w <= wmax; w++) acc |= mt[w] & k64[w];
            bool keep = ((valid32[i >> 5] >> (i & 31)) & 1u) && (acc == 0ull);
            nb1 = __ballot_sync(0xffffffffu, keep);
        }
        if (lane == 0) {
            int w0 = tid >> 5;
            if (nb0 != kw32[w0]) { kw32[w0] = nb0; sChanged = 1; }
            if (tid < 512) {
                int w1 = 32 + (tid >> 5);
                if (nb1 != kw32[w1]) { kw32[w1] = nb1; sChanged = 1; }
            }
        }
        __syncthreads();
        if (!sChanged) break;
    }

    // ---- masked output write ----
    for (int e = tid; e < NBOX*9; e += 1024) {
        int r = e / 9;
        out[e] = g_boxes[e] * (((kw32[r >> 5] >> (r & 31)) & 1u) ? 1.f : 0.f);
    }
    // ---- re-zero selection state for the next run ----
    for (u32 z = tid; z < 3u*NBINP; z += 1024u) g_hist[z] = 0u;
    if (tid < 3) { g_validCount[tid] = 0u; g_selCount[tid] = 0u; g_poolCount[tid] = 0u; }
}

// ---------------- launcher: 6 graph nodes ----------------
extern "C" void kernel_launch(void* const* d_in, const int* in_sizes, int n_in,
                              void* d_out, int out_size) {
    const float* o13 = (const float*)d_in[0];
    const float* o26 = (const float*)d_in[1];
    const float* o52 = (const float*)d_in[2];
    const float* a13 = (const float*)d_in[3];
    const float* a26 = (const float*)d_in[4];
    const float* a52 = (const float*)d_in[5];
    float* out = (float*)d_out;

    k_hist   <<<256, 256>>>(o13, o26, o52);
    k_select <<<256, 256>>>(o13, o26, o52);
    k_sortfix<<<1, 1024>>>();
    k_decode <<<192, 256>>>(o13, o26, o52, a13, a26, a52);
    k_maskT  <<<dim3(24,24), 64>>>();
    k_nms_out<<<1, 1024>>>(out);
    (void)in_sizes; (void)n_in; (void)out_size;
}

// round 17
// speedup vs baseline: 1.2938x; 1.2938x over previous
#include <cuda_runtime.h>
#include <cstdint>

// ---------------- problem constants ----------------
#define TOTAL   340704u        // 16224 + 64896 + 259584 candidates
#define OFF1    16224u
#define OFF2    81120u
#define KSEL    512u
#define NBOX    1536
#define NWORD   24             // 1536/64 mask words per row
#define BINBASE 0xBF199u       // (bits(0.6)|sign)>>12 ; keys for obj in (0.6,1]
#define NBIN    1640u          // 0xBF800 - 0xBF199 + 1
#define NBINP   1664u          // padded
#define POOLCAP 65536u
#define SORTCAP 4096
#define CANDCAP 262144u        // per-scale compacted candidate capacity

typedef unsigned long long u64;
typedef uint32_t u32;

// ---------------- device scratch (static, allocation-free) ----------------
// Zero-initialized at module load; k_nms_out re-zeroes at the end of every
// run, so every execution starts from zeroed state (deterministic).
__device__ u32   g_hist[3*NBINP];
__device__ u32   g_validCount[3];
__device__ u32   g_candCount[3];
__device__ u32   g_selCount[3];
__device__ u32   g_poolCount[3];
__device__ u64   g_cand[3*CANDCAP];  // compacted (key<<32 | orig) per scale
__device__ u64   g_sel[3*512];
__device__ u64   g_pool[3*POOLCAP];
__device__ u64   g_sorted[NBOX];
__device__ float g_boxes[NBOX*9];
__device__ float g_nmsb[NBOX*5];     // x1,y1,x2,y2,area
__device__ int   g_valid[NBOX];
__device__ u64   g_maskT[NBOX*NWORD]; // TRANSPOSED: [col i][row-word w]

// ---------------- shared address/key computation ----------------
__device__ __forceinline__ void cand_addr(u32 i,
        const float* __restrict__ o13, const float* __restrict__ o26,
        const float* __restrict__ o52,
        float& x, int& s, u32& orig) {
    if (i < OFF1) {                 // H=13, HW=169, NHW=5408
        u32 loc = i;
        u32 a = loc / 5408u, r = loc - a*5408u;
        u32 n = r / 169u,  hw = r - n*169u;
        x = o13[(n*255u + a*85u)*169u + hw]; s = 0; orig = r*3u + a;
    } else if (i < OFF2) {          // H=26, HW=676, NHW=21632
        u32 loc = i - OFF1;
        u32 a = loc / 21632u, r = loc - a*21632u;
        u32 n = r / 676u,  hw = r - n*676u;
        x = o26[(n*255u + a*85u)*676u + hw]; s = 1; orig = r*3u + a;
    } else {                        // H=52, HW=2704, NHW=86528
        u32 loc = i - OFF2;
        u32 a = loc / 86528u, r = loc - a*86528u;
        u32 n = r / 2704u, hw = r - n*2704u;
        x = o52[(n*255u + a*85u)*2704u + hw]; s = 2; orig = r*3u + a;
    }
}

// ---------------- K1: histogram + warp-aggregated candidate compaction ----------------
__global__ __launch_bounds__(256) void k_hist(const float* __restrict__ o13,
                                              const float* __restrict__ o26,
                                              const float* __restrict__ o52) {
    __shared__ u32 sh[3*NBINP];
    __shared__ u32 svc[3];
    const u32 t = threadIdx.x;
    const u32 lane = t & 31u;
    for (u32 b = t; b < 3u*NBINP; b += 256u) sh[b] = 0u;
    if (t < 3u) svc[t] = 0u;
    __syncthreads();
    // grid-stride with warp-uniform trip count (base uniform across warp)
    for (u32 base = blockIdx.x*256u; base < TOTAL; base += 65536u) {
        u32 i = base + t;
        bool inb = (i < TOTAL);
        float x = 0.f; int s = 0; u32 orig = 0u;
        if (inb) cand_addr(i, o13, o26, o52, x, s, orig);
        float obj = 1.f / (1.f + expf(-x));
        bool valid = inb && (obj > 0.6f);
        u32 key = 0u;
        if (valid) {
            key = __float_as_uint(obj) | 0x80000000u;
            atomicAdd(&sh[(u32)s*NBINP + ((key >> 12) - BINBASE)], 1u);
            atomicAdd(&svc[s], 1u);
        }
        // warp-aggregated compaction per scale (<=2 distinct scales per warp)
        #pragma unroll
        for (int ss = 0; ss < 3; ss++) {
            u32 m = __ballot_sync(0xffffffffu, valid && (s == ss));
            if (m) {
                u32 leader = (u32)(__ffs(m) - 1);
                u32 pos = 0u;
                if (lane == leader) pos = atomicAdd(&g_candCount[ss], __popc(m));
                pos = __shfl_sync(0xffffffffu, pos, leader);
                if (valid && (s == ss)) {
                    u32 rank = __popc(m & ((1u << lane) - 1u));
                    u32 p = pos + rank;
                    if (p < CANDCAP)
                        g_cand[(u32)ss*CANDCAP + p] = ((u64)key << 32) | orig;
                }
            }
        }
    }
    __syncthreads();
    for (u32 b = t; b < 3u*NBINP; b += 256u) {
        u32 v = sh[b];
        if (v) atomicAdd(&g_hist[b], v);
    }
    if (t < 3u && svc[t]) atomicAdd(&g_validCount[t], svc[t]);
}

// ---------------- K2: select / pool over COMPACTED candidates ----------------
__global__ __launch_bounds__(256) void k_select() {
    __shared__ u32 ss[256];
    __shared__ int shBin[3];
    const u32 t = threadIdx.x;
    // per-scale threshold-bin scan (block-redundant, uniform branches)
    for (int s = 0; s < 3; s++) {
        if (g_validCount[s] < KSEL) {
            if (t == 0) shBin[s] = -2;            // select every valid directly
        } else {
            u32 b0 = t * 7u;
            u32 part = 0u;
            #pragma unroll
            for (u32 k = 0; k < 7u; k++) {
                u32 b = b0 + k;
                if (b < NBIN) part += g_hist[(u32)s*NBINP + b];
            }
            ss[t] = part;
            __syncthreads();
            for (u32 off = 1; off < 256u; off <<= 1) {   // inclusive suffix scan
                u32 add = (t + off < 256u) ? ss[t + off] : 0u;
                __syncthreads();
                ss[t] += add;
                __syncthreads();
            }
            u32 S = ss[t];
            u32 Sn = (t < 255u) ? ss[t + 1] : 0u;
            if (S >= KSEL && Sn < KSEL) {
                u32 cum = Sn;
                for (int k = 6; k >= 0; k--) {
                    u32 b = b0 + (u32)k;
                    if (b < NBIN) {
                        u32 c = g_hist[(u32)s*NBINP + b];
                        cum += c;
                        if (cum >= KSEL) { shBin[s] = (int)b; break; }
                    }
                }
            }
        }
        __syncthreads();
    }
    // scan compacted candidate lists (no input reads, no expf)
    for (int s = 0; s < 3; s++) {
        const int tb = shBin[s];
        u32 cnt = g_candCount[s]; if (cnt > CANDCAP) cnt = CANDCAP;
        const u64* cl = &g_cand[(u32)s*CANDCAP];
        for (u32 j = blockIdx.x*256u + t; j < cnt; j += 65536u) {
            u64 e = cl[j];
            u32 key = (u32)(e >> 32);
            int hidx = (int)((key >> 12) - BINBASE);
            if (hidx > tb) {
                u32 pos = atomicAdd(&g_selCount[s], 1u);
                g_sel[(u32)s*512u + pos] = e;
            } else if (hidx == tb) {
                u32 pos = atomicAdd(&g_poolCount[s], 1u);
                if (pos < POOLCAP)
                    g_pool[(u32)s*POOLCAP + pos] =
                        (e & 0xFFFFFFFF00000000ull) | (u32)(~(u32)e);
            }
        }
    }
}

// ---------------- K3: threshold-bin top-off + global bitonic sort ----------------
__global__ __launch_bounds__(1024) void k_sortfix() {
    __shared__ u64 sm[SORTCAP];        // 32 KB, reused
    __shared__ u32 sTot[3];
    __shared__ u32 scnt, srank;
    const u32 t = threadIdx.x;
    for (int s = 0; s < 3; s++) {
        u32 direct = g_selCount[s];
        u32 valid  = g_validCount[s];
        u32 need   = (valid >= KSEL) ? (KSEL - direct) : 0u;
        if (t == 0) sTot[s] = direct + need;
        u32 n = g_poolCount[s]; if (n > POOLCAP) n = POOLCAP;
        if (need > 0u) {
            if (n <= (u32)SORTCAP) {
                u32 P = 2u; while (P < n) P <<= 1u;
                for (u32 i = t; i < P; i += 1024u)
                    sm[i] = (i < n) ? g_pool[(u32)s*POOLCAP + i] : 0ull;
                __syncthreads();
                for (u32 k = 2; k <= P; k <<= 1)
                    for (u32 j = k >> 1; j > 0; j >>= 1) {
                        for (u32 i = t; i < P; i += 1024u) {
                            u32 ixj = i ^ j;
                            if (ixj > i) {
                                bool desc = ((i & k) == 0u);
                                u64 x = sm[i], y = sm[ixj];
                                if (desc ? (x < y) : (x > y)) { sm[i] = y; sm[ixj] = x; }
                            }
                        }
                        __syncthreads();
                    }
                for (u32 j = t; j < need; j += 1024u) {
                    u64 v = sm[j];
                    g_sel[(u32)s*512u + direct + j] =
                        (v & 0xFFFFFFFF00000000ull) | (u32)(~(u32)v);
                }
            } else {
                // fallback: exact selection via 64-bit binary search (v unique)
                u64 lo = 1ull, hi = 0xFFFFFFFFFFFFFFFFull;
                while (lo < hi) {
                    u64 mid = lo + ((hi - lo + 1ull) >> 1);
                    if (t == 0) scnt = 0u;
                    __syncthreads();
                    u32 c = 0u;
                    for (u32 j = t; j < n; j += 1024u)
                        if (g_pool[(u32)s*POOLCAP + j] >= mid) c++;
                    if (c) atomicAdd(&scnt, c);
                    __syncthreads();
                    u32 total = scnt;
                    __syncthreads();
                    if (total >= need) lo = mid; else hi = mid - 1ull;
                }
                if (t == 0) srank = 0u;
                __syncthreads();
                for (u32 j = t; j < n; j += 1024u) {
                    u64 v = g_pool[(u32)s*POOLCAP + j];
                    if (v >= lo) {
                        u32 p = atomicAdd(&srank, 1u);
                        if (p < need)
                            g_sel[(u32)s*512u + direct + p] =
                                (v & 0xFFFFFFFF00000000ull) | (u32)(~(u32)v);
                    }
                }
            }
        }
        __syncthreads();
    }
    // ---- global sort: 2048-entry bitonic (score desc, concat-pos asc) ----
    const u32 offc[3] = {0u, OFF1, OFF2};
    for (u32 j = t; j < 2048u; j += 1024u) {
        u64 v = 0ull;
        if (j < (u32)NBOX) {
            u32 s = j >> 9, p = j & 511u;
            if (p < sTot[s]) {
                u64 e = g_sel[s*512u + p];
                u32 key  = (u32)(e >> 32);
                u32 gidx = offc[s] + (u32)e;
                v = ((u64)key << 32) | (u32)(~gidx);
            }
        }
        sm[j] = v;
    }
    __syncthreads();
    for (u32 k = 2; k <= 2048u; k <<= 1)
        for (u32 j = k >> 1; j > 0; j >>= 1) {
            for (u32 i = t; i < 2048u; i += 1024u) {
                u32 ixj = i ^ j;
                if (ixj > i) {
                    bool desc = ((i & k) == 0u);
                    u64 x = sm[i], y = sm[ixj];
                    if (desc ? (x < y) : (x > y)) { sm[i] = y; sm[ixj] = x; }
                }
            }
            __syncthreads();
        }
    for (u32 j = t; j < (u32)NBOX; j += 1024u) g_sorted[j] = sm[j];
}

// ---------------- K4: decode winners (one warp per box) ----------------
__global__ void k_decode(const float* __restrict__ o13, const float* __restrict__ o26,
                         const float* __restrict__ o52,
                         const float* __restrict__ a13, const float* __restrict__ a26,
                         const float* __restrict__ a52) {
    int r = (blockIdx.x * blockDim.x + threadIdx.x) >> 5;
    int lane = threadIdx.x & 31;
    if (r >= NBOX) return;
    u64 e = g_sorted[r];
    u32 key = (u32)(e >> 32);
    if (key == 0u) {
        if (lane == 0) {
            #pragma unroll
            for (int k = 0; k < 9; k++) g_boxes[r*9+k] = 0.f;
            #pragma unroll
            for (int k = 0; k < 5; k++) g_nmsb[r*5+k] = 0.f;
            g_valid[r] = 0;
        }
        return;
    }
    u32 gidx = ~(u32)e;
    const float* p; const float* anc; int H; float ts; u32 loc;
    if (gidx < OFF1)      { p=o13; anc=a13; H=13; ts=32.f; loc=gidx; }
    else if (gidx < OFF2) { p=o26; anc=a26; H=26; ts=16.f; loc=gidx-OFF1; }
    else                  { p=o52; anc=a52; H=52; ts=8.f;  loc=gidx-OFF2; }
    u32 a = loc % 3u; u32 q = loc / 3u;
    u32 w = q % (u32)H; q /= (u32)H;
    u32 h = q % (u32)H; u32 n = q / (u32)H;
    int HW = H*H;
    const float* base = p + (size_t)(n*255u + a*85u)*HW + h*H + w;
    float aux = 0.f;
    if (lane >= 1 && lane <= 4) aux = base[lane * HW];
    float bv = -1e30f; int bc = 1 << 30;       // argmax 80 classes, first-max
    for (int c = lane; c < 80; c += 32) {
        float v = base[(5 + c) * HW];
        if (v > bv) { bv = v; bc = c; }
    }
    #pragma unroll
    for (int off = 16; off; off >>= 1) {
        float ov = __shfl_down_sync(0xffffffffu, bv, off);
        int   oc = __shfl_down_sync(0xffffffffu, bc, off);
        if (ov > bv || (ov == bv && oc < bc)) { bv = ov; bc = oc; }
    }
    float v1 = __shfl_sync(0xffffffffu, aux, 1);
    float v2 = __shfl_sync(0xffffffffu, aux, 2);
    float v3 = __shfl_sync(0xffffffffu, aux, 3);
    float v4 = __shfl_sync(0xffffffffu, aux, 4);
    if (lane == 0) {
        float obj = __uint_as_float(key ^ 0x80000000u);
        float cx = ((float)w + v1) * ts / 416.0f;
        float cy = ((float)h + v2) * ts / 416.0f;
        float bw = anc[a*2+0] * expf(v3) / 416.0f;
        float bh = anc[a*2+1] * expf(v4) / 416.0f;
        float* B = &g_boxes[r*9];
        B[0]=(float)n; B[1]=cx; B[2]=cy; B[3]=bw; B[4]=bh;
        B[5]=obj; B[6]=(float)bc; B[7]=(float)h; B[8]=(float)w;
        float x1 = cx - bw*0.5f, y1 = cy - bh*0.5f;
        float x2 = cx + bw*0.5f, y2 = cy + bh*0.5f;
        float area = fmaxf(x2-x1, 0.f) * fmaxf(y2-y1, 0.f);
        float* Nn = &g_nmsb[r*5];
        Nn[0]=x1; Nn[1]=y1; Nn[2]=x2; Nn[3]=y2; Nn[4]=area;
        g_valid[r] = 1;
    }
}

// ---------------- K5: TRANSPOSED suppression bitmask ----------------
// g_maskT[c][rb] bit j = (row rb*64+j) < c  AND  iou(row, col c) > 0.7
__global__ void k_maskT() {
    int rb = blockIdx.x, cb = blockIdx.y;   // row block (suppressors), col block
    __shared__ float r0[64], r1[64], r2[64], r3[64], ra[64];
    int t = threadIdx.x;
    int rr = rb*64 + t;
    r0[t]=g_nmsb[rr*5+0]; r1[t]=g_nmsb[rr*5+1]; r2[t]=g_nmsb[rr*5+2];
    r3[t]=g_nmsb[rr*5+3]; ra[t]=g_nmsb[rr*5+4];
    __syncthreads();
    int c = cb*64 + t;
    float x1=g_nmsb[c*5+0], y1=g_nmsb[c*5+1], x2=g_nmsb[c*5+2],
          y2=g_nmsb[c*5+3], ar=g_nmsb[c*5+4];
    u64 bits = 0ull;
    #pragma unroll 4
    for (int j = 0; j < 64; j++) {
        int rj = rb*64 + j;
        if (rj < c) {
            float ix = fmaxf(fminf(x2, r2[j]) - fmaxf(x1, r0[j]), 0.f);
            float iy = fmaxf(fminf(y2, r3[j]) - fmaxf(y1, r1[j]), 0.f);
            float iou = (ix * iy) / fmaxf(fminf(ar, ra[j]), 1e-9f);
            if (iou > 0.7f) bits |= (1ull << j);
        }
    }
    g_maskT[c*NWORD + rb] = bits;
}

// ---------------- K6: NMS via exact Jacobi fixpoint + output + re-zero ----------------
// k <- valid; iterate k <- T(k), T(k)[i] = valid[i] & !OR_{j<i}(k[j] & M[j][i]).
// Unique fixpoint = greedy NMS result; correct prefix grows every iteration.
__global__ __launch_bounds__(1024) void k_nms_out(float* __restrict__ out) {
    __shared__ u32 kw32[48];
    __shared__ u32 valid32[48];
    __shared__ u64 k64[NWORD];
    __shared__ int sChanged;
    const int tid  = threadIdx.x;
    const int lane = tid & 31;

    {
        int i = tid;                               // boxes 0..1023
        u32 b = __ballot_sync(0xffffffffu, g_valid[i] != 0);
        if (lane == 0) { valid32[tid >> 5] = b; kw32[tid >> 5] = b; }
        if (tid < 512) {
            int i2 = 1024 + tid;                   // boxes 1024..1535
            u32 b2 = __ballot_sync(0xffffffffu, g_valid[i2] != 0);
            if (lane == 0) { valid32[32 + (tid >> 5)] = b2; kw32[32 + (tid >> 5)] = b2; }
        }
    }
    __syncthreads();

    for (int it = 0; it < NBOX; it++) {
        if (tid < NWORD) k64[tid] = (u64)kw32[2*tid] | ((u64)kw32[2*tid+1] << 32);
        if (tid == 0) sChanged = 0;
        __syncthreads();
        u32 nb0, nb1 = 0u;
        {
            int i = tid;
            u64 acc = 0ull;
            int wmax = i >> 6;
            const u64* mt = &g_maskT[(size_t)i * NWORD];
            for (int w = 0; w <= wmax; w++) acc |= mt[w] & k64[w];
            bool keep = ((valid32[i >> 5] >> (i & 31)) & 1u) && (acc == 0ull);
            nb0 = __ballot_sync(0xffffffffu, keep);
        }
        if (tid < 512) {
            int i = 1024 + tid;
            u64 acc = 0ull;
            int wmax = i >> 6;
            const u64* mt = &g_maskT[(size_t)i * NWORD];
            for (int w = 0; w <= wmax; w++) acc |= mt[w] & k64[w];
            bool keep = ((valid32[i >> 5] >> (i & 31)) & 1u) && (acc == 0ull);
            nb1 = __ballot_sync(0xffffffffu, keep);
        }
        if (lane == 0) {
            int w0 = tid >> 5;
            if (nb0 != kw32[w0]) { kw32[w0] = nb0; sChanged = 1; }
            if (tid < 512) {
                int w1 = 32 + (tid >> 5);
                if (nb1 != kw32[w1]) { kw32[w1] = nb1; sChanged = 1; }
            }
        }
        __syncthreads();
        if (!sChanged) break;
    }

    // ---- masked output write ----
    for (int e = tid; e < NBOX*9; e += 1024) {
        int r = e / 9;
        out[e] = g_boxes[e] * (((kw32[r >> 5] >> (r & 31)) & 1u) ? 1.f : 0.f);
    }
    // ---- re-zero selection state for the next run ----
    for (u32 z = tid; z < 3u*NBINP; z += 1024u) g_hist[z] = 0u;
    if (tid < 3) {
        g_validCount[tid] = 0u; g_candCount[tid] = 0u;
        g_selCount[tid] = 0u;   g_poolCount[tid] = 0u;
    }
}

// ---------------- launcher: 6 graph nodes ----------------
extern "C" void kernel_launch(void* const* d_in, const int* in_sizes, int n_in,
                              void* d_out, int out_size) {
    const float* o13 = (const float*)d_in[0];
    const float* o26 = (const float*)d_in[1];
    const float* o52 = (const float*)d_in[2];
    const float* a13 = (const float*)d_in[3];
    const float* a26 = (const float*)d_in[4];
    const float* a52 = (const float*)d_in[5];
    float* out = (float*)d_out;

    k_hist   <<<256, 256>>>(o13, o26, o52);
    k_select <<<256, 256>>>();
    k_sortfix<<<1, 1024>>>();
    k_decode <<<192, 256>>>(o13, o26, o52, a13, a26, a52);
    k_maskT  <<<dim3(24,24), 64>>>();
    k_nms_out<<<1, 1024>>>(out);
    (void)in_sizes; (void)n_in; (void)out_size;
}